// round 10
// baseline (speedup 1.0000x reference)
#include <cuda_runtime.h>
#include <cuda_bf16.h>

// Problem constants
#define B 64
#define L 512
#define T 8
#define D 1024
#define C 3
#define N_HOPS 6
#define LS 8
#define LCHUNK 64
#define NATTN (B * LS)
#define CHAIN_BLOCKS 512

// ---------------- device scratch ----------------
__device__ float g_P[7][4][D];          // projection chains: [k][0]=W^k wa2, [k][1+m]=W^k Wout[:,m]
__device__ float g_c[5][B][L];          // c_k[b,l] = p_k . emb_row
__device__ float g_smb[B][L];           // v_loc * (emb . wa1)
__device__ float g_vloc[B][L];
__device__ float g_vec[B][D];           // v_aspect (vec_0)
__device__ float g_aw6[N_HOPS][B][L];   // alpha*v_loc per hop
__device__ float g_cp[LS][B][6][D];     // phase-C split-L partials (12.6 MB)
__device__ float g_a[6][B][D];          // a_j = attn_out at hop j
__device__ int g_bar_count;             // zero-initialized
__device__ int g_bar_phase;

__device__ __forceinline__ float dot4(const float4 a, const float4 b) {
    return a.x * b.x + a.y * b.y + a.z * b.z + a.w * b.w;
}

// ---------------- software grid barrier (sense reversal) -------------------------
// Safe: CHAIN_BLOCKS=512 blocks x 256 thr (<=4/SM) are all co-resident in wave 1.
__device__ __forceinline__ void grid_barrier() {
    __syncthreads();
    if (threadIdx.x == 0) {
        volatile int* ph = &g_bar_phase;
        int phase = *ph;
        __threadfence();
        if (atomicAdd(&g_bar_count, 1) == CHAIN_BLOCKS - 1) {
            g_bar_count = 0;
            __threadfence();
            *ph = phase ^ 1;
        } else {
            while (*ph == phase) { }
        }
        __threadfence();
    }
    __syncthreads();
}

// ---------------- reduction helpers (512-thread blocks) --------------------------
template <int NV>
__device__ __forceinline__ void block_multired(float* v, float* scratch /*16*NV*/,
                                               float* out /*NV*/, int tid) {
    int lane = tid & 31, wid = tid >> 5;
    #pragma unroll
    for (int i = 0; i < NV; i++)
        #pragma unroll
        for (int o = 16; o > 0; o >>= 1)
            v[i] += __shfl_xor_sync(0xffffffffu, v[i], o);
    if (lane == 0)
        #pragma unroll
        for (int i = 0; i < NV; i++) scratch[wid * NV + i] = v[i];
    __syncthreads();
    if (tid < NV) {
        float s = 0.f;
        #pragma unroll
        for (int w = 0; w < 16; w++) s += scratch[w * NV + tid];
        out[tid] = s;
    }
    __syncthreads();
}

__device__ __forceinline__ float block_max512(float v, float* mscr /*33*/, int tid) {
    int lane = tid & 31, wid = tid >> 5;
    #pragma unroll
    for (int o = 16; o > 0; o >>= 1)
        v = fmaxf(v, __shfl_xor_sync(0xffffffffu, v, o));
    if (lane == 0) mscr[wid] = v;
    __syncthreads();
    if (tid < 32) {
        float m = (tid < 16) ? mscr[tid] : -1e30f;
        #pragma unroll
        for (int o = 8; o > 0; o >>= 1)
            m = fmaxf(m, __shfl_xor_sync(0xffffffffu, m, o));
        if (tid == 0) mscr[32] = m;
    }
    __syncthreads();
    float r = mscr[32];
    __syncthreads();
    return r;
}

// ---------------- kernel: init projection chain (k=0) ----------------------------
__global__ void proj_init_k(const float* __restrict__ wattn,
                            const float* __restrict__ Wout) {
    int d = blockIdx.x * 256 + threadIdx.x;
    g_P[0][0][d] = wattn[D + d];
    #pragma unroll
    for (int m = 0; m < C; m++) g_P[0][1 + m][d] = Wout[d * C + m];
}

// ---------------- kernel: FUSED chain — all 6 steps, one launch ------------------
// grid CHAIN_BLOCKS=512, 256 threads. Block owns rows {2*bid, 2*bid+1}.
// Threads 0-127 -> row 0 half, 128-255 -> row 1; each thread covers 8 floats.
__global__ void __launch_bounds__(256) chain_k(const float* __restrict__ W) {
    int tid = threadIdx.x;
    int half = tid >> 7;          // which of the block's 2 rows
    int j = tid & 127;            // 8-float slice index within row
    int r = blockIdx.x * 2 + half;
    const float4* wrow = (const float4*)(W + (long)r * D);
    __shared__ float scr[8][4];   // [warp][chain column]

    for (int k = 0; k < 6; k++) {
        float4 w0 = wrow[j * 2];
        float4 w1 = wrow[j * 2 + 1];
        float a[4];
        #pragma unroll
        for (int c = 0; c < 4; c++) {
            const float4* p4 = (const float4*)g_P[k][c];
            a[c] = dot4(w0, p4[j * 2]) + dot4(w1, p4[j * 2 + 1]);
        }
        #pragma unroll
        for (int c = 0; c < 4; c++)
            #pragma unroll
            for (int o = 16; o > 0; o >>= 1)
                a[c] += __shfl_xor_sync(0xffffffffu, a[c], o);
        int lane = tid & 31, wid = tid >> 5;
        if (lane == 0)
            #pragma unroll
            for (int c = 0; c < 4; c++) scr[wid][c] = a[c];
        __syncthreads();
        if (j < 4) {
            // sum the 4 warps of this half
            int w0i = half * 4;
            float s = scr[w0i][j] + scr[w0i + 1][j] + scr[w0i + 2][j] + scr[w0i + 3][j];
            g_P[k + 1][j][r] = s;
        }
        if (k < 5) grid_barrier();    // makes g_P[k+1] globally visible
    }
}

// ---------------- kernel: pass A — per-row dots (wa1, p_0..p_4), vloc, smb -------
// grid (B, L/8), 256 threads, warp per row
__global__ void precomputeA_k(const int* __restrict__ ctx,
                              const int* __restrict__ clen,
                              const int* __restrict__ toff,
                              const float* __restrict__ emb,
                              const float* __restrict__ wattn) {
    int b = blockIdx.x;
    int l = blockIdx.y * 8 + (threadIdx.x >> 5);
    int lane = threadIdx.x & 31;
    int len = clen[b];

    if (l < len) {
        int id = ctx[b * L + l];
        const float4* e4 = (const float4*)(emb + (long)id * D);
        float4 e[8];
        #pragma unroll
        for (int i = 0; i < 8; i++) e[i] = e4[i * 32 + lane];

        float acc[6] = {};
        #pragma unroll
        for (int i = 0; i < 8; i++) {
            acc[0] += dot4(e[i], ((const float4*)wattn)[i * 32 + lane]);
            acc[1] += dot4(e[i], ((const float4*)g_P[0][0])[i * 32 + lane]);
            acc[2] += dot4(e[i], ((const float4*)g_P[1][0])[i * 32 + lane]);
            acc[3] += dot4(e[i], ((const float4*)g_P[2][0])[i * 32 + lane]);
            acc[4] += dot4(e[i], ((const float4*)g_P[3][0])[i * 32 + lane]);
            acc[5] += dot4(e[i], ((const float4*)g_P[4][0])[i * 32 + lane]);
        }
        #pragma unroll
        for (int jj = 0; jj < 6; jj++)
            #pragma unroll
            for (int o = 16; o > 0; o >>= 1)
                acc[jj] += __shfl_xor_sync(0xffffffffu, acc[jj], o);

        if (lane == 0) {
            float v = 1.0f - fabsf((float)(l - toff[b])) / (float)len;
            g_vloc[b][l] = v;
            g_smb[b][l] = v * acc[0];
            g_c[0][b][l] = acc[1];
            g_c[1][b][l] = acc[2];
            g_c[2][b][l] = acc[3];
            g_c[3][b][l] = acc[4];
            g_c[4][b][l] = acc[5];
        }
    } else if (lane == 0) {
        g_vloc[b][l] = 0.f;
        g_smb[b][l] = 0.f;
        #pragma unroll
        for (int k = 0; k < 5; k++) g_c[k][b][l] = 0.f;
    }
}

// ---------------- kernel: v_aspect -> g_vec --------------------------------------
__global__ void vaspect_k(const int* __restrict__ tgt,
                          const int* __restrict__ tlen,
                          const float* __restrict__ emb) {
    int b = blockIdx.x, t = threadIdx.x;
    int n = tlen[b];
    float4 acc = make_float4(0.f, 0.f, 0.f, 0.f);
    #pragma unroll
    for (int i = 0; i < T; i++) {
        if (i < n) {
            int id = tgt[b * T + i];
            float4 e = ((const float4*)(emb + (long)id * D))[t];
            acc.x += e.x; acc.y += e.y; acc.z += e.z; acc.w += e.w;
        }
    }
    float inv = 1.0f / (float)n;
    acc.x *= inv; acc.y *= inv; acc.z *= inv; acc.w *= inv;
    ((float4*)g_vec[b])[t] = acc;
}

// ---------------- kernel: scalar hop recurrence -> all aw_h -----------------------
// grid B, 512 threads (one per l)
__global__ void scalar_k(const int* __restrict__ clen,
                         const float* __restrict__ blin,
                         const float* __restrict__ battn) {
    int b = blockIdx.x, t = threadIdx.x;
    __shared__ float scr[16 * 12];
    __shared__ float res12[12];
    __shared__ float mscr[33];
    __shared__ float t_arr[6];
    __shared__ float beta[6];
    __shared__ float A[5];

    // t_k^0 = p_k . v0 ; beta_k = p_k . blin   (k = 0..5)
    {
        float vals[12];
        int d = t * 2;
        float2 v0 = *(const float2*)&g_vec[b][d];
        float2 bl = *(const float2*)&blin[d];
        #pragma unroll
        for (int k = 0; k < 6; k++) {
            float2 p = *(const float2*)&g_P[k][0][d];
            vals[k] = p.x * v0.x + p.y * v0.y;
            vals[6 + k] = p.x * bl.x + p.y * bl.y;
        }
        block_multired<12>(vals, scr, res12, t);
        if (t < 6) { t_arr[t] = res12[t]; beta[t] = res12[6 + t]; }
        __syncthreads();
    }

    int len = clen[b];
    bool valid = t < len;
    float smb_l = g_smb[b][t];
    float vloc_l = g_vloc[b][t];
    float cv[5];
    #pragma unroll
    for (int k = 0; k < 5; k++) cv[k] = g_c[k][b][t];
    float bat = battn[0];

    for (int h = 0; h < N_HOPS; h++) {
        float s = t_arr[0];
        float sc = valid ? tanhf(smb_l + s + bat) : -1e30f;
        float mx = block_max512(sc, mscr, t);
        float e = valid ? expf(sc - mx) : 0.f;
        {
            float v1[1] = {e};
            block_multired<1>(v1, scr, res12, t);
        }
        float aw = (e / res12[0]) * vloc_l;
        g_aw6[h][b][t] = aw;

        float pv[5];
        #pragma unroll
        for (int k = 0; k < 5; k++) pv[k] = aw * cv[k];
        block_multired<5>(pv, scr, A, t);

        if (t == 0) {
            #pragma unroll
            for (int k = 0; k < 5; k++)       // ascending: reads t_arr[k+1] pre-update
                t_arr[k] = A[k] + t_arr[k + 1] + beta[k];
        }
        __syncthreads();
    }
}

// ---------------- kernel: pass C — 6-way weighted sums (split L) -----------------
// grid NATTN=512 blocks, 256 threads; block=(b,ls)
__global__ void phaseC_k(const int* __restrict__ ctx,
                         const int* __restrict__ clen,
                         const float* __restrict__ emb) {
    int bid = blockIdx.x;
    int b = bid & (B - 1);
    int ls = bid >> 6;
    int tid = threadIdx.x;
    __shared__ int ids[LCHUNK];
    __shared__ float w[6][LCHUNK];

    int l0 = ls * LCHUNK;
    if (tid < LCHUNK) ids[tid] = ctx[b * L + l0 + tid];
    for (int i = tid; i < 6 * LCHUNK; i += 256) {
        int j = i >> 6, li = i & (LCHUNK - 1);
        w[j][li] = g_aw6[j][b][l0 + li];
    }
    __syncthreads();

    int len = clen[b];
    int lend = len - l0;
    if (lend > LCHUNK) lend = LCHUNK;
    if (lend < 0) lend = 0;

    float4 acc[6] = {};
    const float4* e4 = (const float4*)emb;
    #pragma unroll 4
    for (int i = 0; i < lend; i++) {
        float4 ev = e4[(long)ids[i] * 256 + tid];
        #pragma unroll
        for (int j = 0; j < 6; j++) {
            float wj = w[j][i];
            acc[j].x += wj * ev.x;
            acc[j].y += wj * ev.y;
            acc[j].z += wj * ev.z;
            acc[j].w += wj * ev.w;
        }
    }
    #pragma unroll
    for (int j = 0; j < 6; j++)
        *(float4*)&g_cp[ls][b][j][tid * 4] = acc[j];
}

// ---------------- kernel: combine phase-C partials -> g_a ------------------------
// grid 6*B, 256 threads
__global__ void combineC_k() {
    int bid = blockIdx.x;
    int b = bid & (B - 1);
    int j = bid >> 6;
    int t = threadIdx.x;
    float4 s = make_float4(0.f, 0.f, 0.f, 0.f);
    #pragma unroll
    for (int ls = 0; ls < LS; ls++) {
        float4 p = *(const float4*)&g_cp[ls][b][j][t * 4];
        s.x += p.x; s.y += p.y; s.z += p.z; s.w += p.w;
    }
    *(float4*)&g_a[j][b][t * 4] = s;
}

// ---------------- kernel: final logits -------------------------------------------
// grid B, 512 threads (float2 per thread)
__global__ void logits_k(const float* __restrict__ blin,
                         const float* __restrict__ bout,
                         float* __restrict__ out) {
    int b = blockIdx.x, t = threadIdx.x;
    __shared__ float scr[16 * 3];
    __shared__ float res[3];

    int d = t * 2;
    float2 v0 = *(const float2*)&g_vec[b][d];
    float2 bl = *(const float2*)&blin[d];

    float pm[3] = {};
    #pragma unroll
    for (int m = 0; m < C; m++) {
        #pragma unroll
        for (int j = 0; j < 6; j++) {
            float2 u = *(const float2*)&g_P[5 - j][1 + m][d];
            float2 a = *(const float2*)&g_a[j][b][d];
            pm[m] += u.x * a.x + u.y * a.y;
        }
        float2 u6 = *(const float2*)&g_P[6][1 + m][d];
        pm[m] += u6.x * v0.x + u6.y * v0.y;
        #pragma unroll
        for (int k = 0; k < 6; k++) {
            float2 uk = *(const float2*)&g_P[k][1 + m][d];
            pm[m] += uk.x * bl.x + uk.y * bl.y;
        }
    }
    block_multired<3>(pm, scr, res, t);
    if (t < C) out[b * C + t] = res[t] + bout[t];
}

// ---------------- launcher -------------------------------------------------------
extern "C" void kernel_launch(void* const* d_in, const int* in_sizes, int n_in,
                              void* d_out, int out_size) {
    const int*   ctx   = (const int*)d_in[0];
    const int*   tgt   = (const int*)d_in[1];
    const int*   clen  = (const int*)d_in[2];
    const int*   tlen  = (const int*)d_in[3];
    const int*   toff  = (const int*)d_in[4];
    const float* emb   = (const float*)d_in[5];
    const float* Wlin  = (const float*)d_in[6];
    const float* blin  = (const float*)d_in[7];
    const float* wattn = (const float*)d_in[8];
    const float* battn = (const float*)d_in[9];
    const float* Wout  = (const float*)d_in[10];
    const float* bout  = (const float*)d_in[11];
    float* out = (float*)d_out;

    proj_init_k<<<4, 256>>>(wattn, Wout);
    vaspect_k<<<B, 256>>>(tgt, tlen, emb);
    chain_k<<<CHAIN_BLOCKS, 256>>>(Wlin);
    precomputeA_k<<<dim3(B, L / 8), 256>>>(ctx, clen, toff, emb, wattn);
    scalar_k<<<B, 512>>>(clen, blin, battn);
    phaseC_k<<<NATTN, 256>>>(ctx, clen, emb);
    combineC_k<<<6 * B, 256>>>();
    logits_k<<<B, 512>>>(blin, bout, out);
}

// round 11
// speedup vs baseline: 1.1345x; 1.1345x over previous
#include <cuda_runtime.h>
#include <cuda_bf16.h>

// Problem constants
#define B 64
#define L 512
#define T 8
#define D 1024
#define C 3
#define N_HOPS 6
#define LS 8
#define LCHUNK 64
#define NATTN (B * LS)

// ---------------- device scratch ----------------
__device__ float g_P[7][4][D];          // projection chains: [k][0]=W^k wa2, [k][1+m]=W^k Wout[:,m]
__device__ float g_c[5][B][L];          // c_k[b,l] = p_k . emb_row
__device__ float g_smb[B][L];           // v_loc * (emb . wa1)
__device__ float g_vloc[B][L];
__device__ float g_vec[B][D];           // v_aspect (vec_0)
__device__ float g_aw6[N_HOPS][B][L];   // alpha*v_loc per hop
__device__ float g_cp[LS][B][6][D];     // phase-C split-L partials
__device__ float g_a[6][B][D];          // a_j = attn_out at hop j

__device__ __forceinline__ float dot4(const float4 a, const float4 b) {
    return a.x * b.x + a.y * b.y + a.z * b.z + a.w * b.w;
}

// packed f32x2 fma: d += a*b (elementwise on 2 floats)
__device__ __forceinline__ void ffma2(unsigned long long& d, unsigned long long a,
                                      unsigned long long b) {
    asm("fma.rn.f32x2 %0, %1, %2, %0;" : "+l"(d) : "l"(a), "l"(b));
}

union F4U2 {
    float4 f;
    unsigned long long u[2];
};

// ---------------- reduction helpers (512-thread blocks) --------------------------
template <int NV>
__device__ __forceinline__ void block_multired(float* v, float* scratch /*16*NV*/,
                                               float* out /*NV*/, int tid) {
    int lane = tid & 31, wid = tid >> 5;
    #pragma unroll
    for (int i = 0; i < NV; i++)
        #pragma unroll
        for (int o = 16; o > 0; o >>= 1)
            v[i] += __shfl_xor_sync(0xffffffffu, v[i], o);
    if (lane == 0)
        #pragma unroll
        for (int i = 0; i < NV; i++) scratch[wid * NV + i] = v[i];
    __syncthreads();
    if (tid < NV) {
        float s = 0.f;
        #pragma unroll
        for (int w = 0; w < 16; w++) s += scratch[w * NV + tid];
        out[tid] = s;
    }
    __syncthreads();
}

__device__ __forceinline__ float block_max512(float v, float* mscr /*33*/, int tid) {
    int lane = tid & 31, wid = tid >> 5;
    #pragma unroll
    for (int o = 16; o > 0; o >>= 1)
        v = fmaxf(v, __shfl_xor_sync(0xffffffffu, v, o));
    if (lane == 0) mscr[wid] = v;
    __syncthreads();
    if (tid < 32) {
        float m = (tid < 16) ? mscr[tid] : -1e30f;
        #pragma unroll
        for (int o = 8; o > 0; o >>= 1)
            m = fmaxf(m, __shfl_xor_sync(0xffffffffu, m, o));
        if (tid == 0) mscr[32] = m;
    }
    __syncthreads();
    float r = mscr[32];
    __syncthreads();
    return r;
}

// ---------------- kernel: init projection chain (k=0) ----------------------------
__global__ void proj_init_k(const float* __restrict__ wattn,
                            const float* __restrict__ Wout) {
    int d = blockIdx.x * 256 + threadIdx.x;
    g_P[0][0][d] = wattn[D + d];
    #pragma unroll
    for (int m = 0; m < C; m++) g_P[0][1 + m][d] = Wout[d * C + m];
}

// ---------------- kernel: one chain step (R9 proven config) ----------------------
// grid 1024 (block per output row), 256 threads
__global__ void matvec4_k(const float* __restrict__ W, int k) {
    int r = blockIdx.x;
    int t = threadIdx.x;
    __shared__ float scr[8 * 4];

    float4 w = ((const float4*)(W + (long)r * D))[t];
    float a[4];
    #pragma unroll
    for (int c = 0; c < 4; c++)
        a[c] = dot4(w, ((const float4*)g_P[k][c])[t]);

    #pragma unroll
    for (int c = 0; c < 4; c++)
        #pragma unroll
        for (int o = 16; o > 0; o >>= 1)
            a[c] += __shfl_xor_sync(0xffffffffu, a[c], o);

    int lane = t & 31, wid = t >> 5;
    if (lane == 0)
        #pragma unroll
        for (int c = 0; c < 4; c++) scr[wid * 4 + c] = a[c];
    __syncthreads();
    if (t < 4) {
        float s = 0.f;
        #pragma unroll
        for (int w8 = 0; w8 < 8; w8++) s += scr[w8 * 4 + t];
        g_P[k + 1][t][r] = s;
    }
}

// ---------------- kernel: pass A v2 — smem-p, 4 rows/warp, packed fma ------------
// grid (B, L/32), 256 threads = 8 warps; warp handles 4 consecutive rows.
__global__ void __launch_bounds__(256) precomputeA_k(const int* __restrict__ ctx,
                                                     const int* __restrict__ clen,
                                                     const int* __restrict__ toff,
                                                     const float* __restrict__ emb,
                                                     const float* __restrict__ wattn) {
    __shared__ float4 sp4[6 * 256];   // 6 vectors x 1024 floats = 24 KB
    int tid = threadIdx.x;
    int b = blockIdx.x;

    // stage the 6 projection vectors: [0]=wa1, [1..5]=g_P[0..4][0]
    #pragma unroll
    for (int i = tid; i < 6 * 256; i += 256) {
        int k = i >> 8, pos = i & 255;
        const float4* src = (k == 0) ? (const float4*)wattn
                                     : (const float4*)g_P[k - 1][0];
        sp4[i] = src[pos];
    }
    __syncthreads();

    int lane = tid & 31, warp = tid >> 5;
    int len = clen[b];
    int tofs = toff[b];
    int lbase = blockIdx.y * 32 + warp * 4;

    // row pointers + validity
    const float4* erow[4];
    bool valid[4];
    #pragma unroll
    for (int r = 0; r < 4; r++) {
        int l = lbase + r;
        valid[r] = (l < len);
        erow[r] = (const float4*)(emb + (long)ctx[b * L + l] * D);
    }

    unsigned long long acc2[6][4] = {};
    const float4 z4 = make_float4(0.f, 0.f, 0.f, 0.f);

    #pragma unroll
    for (int i = 0; i < 8; i++) {
        F4U2 e[4];
        #pragma unroll
        for (int r = 0; r < 4; r++)
            e[r].f = valid[r] ? erow[r][i * 32 + lane] : z4;
        #pragma unroll
        for (int k = 0; k < 6; k++) {
            F4U2 p;
            p.f = sp4[k * 256 + i * 32 + lane];
            #pragma unroll
            for (int r = 0; r < 4; r++) {
                ffma2(acc2[k][r], p.u[0], e[r].u[0]);
                ffma2(acc2[k][r], p.u[1], e[r].u[1]);
            }
        }
    }

    // collapse packed pairs, then warp-reduce the 24 scalars
    float s[6][4];
    #pragma unroll
    for (int k = 0; k < 6; k++)
        #pragma unroll
        for (int r = 0; r < 4; r++) {
            float2 t2 = *(float2*)&acc2[k][r];
            float v = t2.x + t2.y;
            #pragma unroll
            for (int o = 16; o > 0; o >>= 1)
                v += __shfl_xor_sync(0xffffffffu, v, o);
            s[k][r] = v;
        }

    if (lane == 0) {
        #pragma unroll
        for (int r = 0; r < 4; r++) {
            int l = lbase + r;
            float v = valid[r]
                        ? 1.0f - fabsf((float)(l - tofs)) / (float)len
                        : 0.f;
            g_vloc[b][l] = v;
            g_smb[b][l] = v * s[0][r];
            g_c[0][b][l] = s[1][r];
            g_c[1][b][l] = s[2][r];
            g_c[2][b][l] = s[3][r];
            g_c[3][b][l] = s[4][r];
            g_c[4][b][l] = s[5][r];
        }
    }
}

// ---------------- kernel: v_aspect -> g_vec --------------------------------------
__global__ void vaspect_k(const int* __restrict__ tgt,
                          const int* __restrict__ tlen,
                          const float* __restrict__ emb) {
    int b = blockIdx.x, t = threadIdx.x;
    int n = tlen[b];
    float4 acc = make_float4(0.f, 0.f, 0.f, 0.f);
    #pragma unroll
    for (int i = 0; i < T; i++) {
        if (i < n) {
            int id = tgt[b * T + i];
            float4 e = ((const float4*)(emb + (long)id * D))[t];
            acc.x += e.x; acc.y += e.y; acc.z += e.z; acc.w += e.w;
        }
    }
    float inv = 1.0f / (float)n;
    acc.x *= inv; acc.y *= inv; acc.z *= inv; acc.w *= inv;
    ((float4*)g_vec[b])[t] = acc;
}

// ---------------- kernel: scalar hop recurrence -> all aw_h -----------------------
// grid B, 512 threads (one per l)
__global__ void scalar_k(const int* __restrict__ clen,
                         const float* __restrict__ blin,
                         const float* __restrict__ battn) {
    int b = blockIdx.x, t = threadIdx.x;
    __shared__ float scr[16 * 12];
    __shared__ float res12[12];
    __shared__ float mscr[33];
    __shared__ float t_arr[6];
    __shared__ float beta[6];
    __shared__ float A[5];

    {
        float vals[12];
        int d = t * 2;
        float2 v0 = *(const float2*)&g_vec[b][d];
        float2 bl = *(const float2*)&blin[d];
        #pragma unroll
        for (int k = 0; k < 6; k++) {
            float2 p = *(const float2*)&g_P[k][0][d];
            vals[k] = p.x * v0.x + p.y * v0.y;
            vals[6 + k] = p.x * bl.x + p.y * bl.y;
        }
        block_multired<12>(vals, scr, res12, t);
        if (t < 6) { t_arr[t] = res12[t]; beta[t] = res12[6 + t]; }
        __syncthreads();
    }

    int len = clen[b];
    bool valid = t < len;
    float smb_l = g_smb[b][t];
    float vloc_l = g_vloc[b][t];
    float cv[5];
    #pragma unroll
    for (int k = 0; k < 5; k++) cv[k] = g_c[k][b][t];
    float bat = battn[0];

    for (int h = 0; h < N_HOPS; h++) {
        float s = t_arr[0];
        float sc = valid ? tanhf(smb_l + s + bat) : -1e30f;
        float mx = block_max512(sc, mscr, t);
        float e = valid ? expf(sc - mx) : 0.f;
        {
            float v1[1] = {e};
            block_multired<1>(v1, scr, res12, t);
        }
        float aw = (e / res12[0]) * vloc_l;
        g_aw6[h][b][t] = aw;

        float pv[5];
        #pragma unroll
        for (int k = 0; k < 5; k++) pv[k] = aw * cv[k];
        block_multired<5>(pv, scr, A, t);

        if (t == 0) {
            #pragma unroll
            for (int k = 0; k < 5; k++)
                t_arr[k] = A[k] + t_arr[k + 1] + beta[k];
        }
        __syncthreads();
    }
}

// ---------------- kernel: pass C — 6-way weighted sums (split L) -----------------
// grid NATTN=512 blocks, 256 threads; block=(b,ls)
__global__ void phaseC_k(const int* __restrict__ ctx,
                         const int* __restrict__ clen,
                         const float* __restrict__ emb) {
    int bid = blockIdx.x;
    int b = bid & (B - 1);
    int ls = bid >> 6;
    int tid = threadIdx.x;
    __shared__ int ids[LCHUNK];
    __shared__ float w[6][LCHUNK];

    int l0 = ls * LCHUNK;
    if (tid < LCHUNK) ids[tid] = ctx[b * L + l0 + tid];
    for (int i = tid; i < 6 * LCHUNK; i += 256) {
        int j = i >> 6, li = i & (LCHUNK - 1);
        w[j][li] = g_aw6[j][b][l0 + li];
    }
    __syncthreads();

    int len = clen[b];
    int lend = len - l0;
    if (lend > LCHUNK) lend = LCHUNK;
    if (lend < 0) lend = 0;

    float4 acc[6] = {};
    const float4* e4 = (const float4*)emb;
    #pragma unroll 4
    for (int i = 0; i < lend; i++) {
        float4 ev = e4[(long)ids[i] * 256 + tid];
        #pragma unroll
        for (int j = 0; j < 6; j++) {
            float wj = w[j][i];
            acc[j].x += wj * ev.x;
            acc[j].y += wj * ev.y;
            acc[j].z += wj * ev.z;
            acc[j].w += wj * ev.w;
        }
    }
    #pragma unroll
    for (int j = 0; j < 6; j++)
        *(float4*)&g_cp[ls][b][j][tid * 4] = acc[j];
}

// ---------------- kernel: combine phase-C partials -> g_a ------------------------
// grid 6*B, 256 threads
__global__ void combineC_k() {
    int bid = blockIdx.x;
    int b = bid & (B - 1);
    int j = bid >> 6;
    int t = threadIdx.x;
    float4 s = make_float4(0.f, 0.f, 0.f, 0.f);
    #pragma unroll
    for (int ls = 0; ls < LS; ls++) {
        float4 p = *(const float4*)&g_cp[ls][b][j][t * 4];
        s.x += p.x; s.y += p.y; s.z += p.z; s.w += p.w;
    }
    *(float4*)&g_a[j][b][t * 4] = s;
}

// ---------------- kernel: final logits -------------------------------------------
// grid B, 512 threads (float2 per thread)
__global__ void logits_k(const float* __restrict__ blin,
                         const float* __restrict__ bout,
                         float* __restrict__ out) {
    int b = blockIdx.x, t = threadIdx.x;
    __shared__ float scr[16 * 3];
    __shared__ float res[3];

    int d = t * 2;
    float2 v0 = *(const float2*)&g_vec[b][d];
    float2 bl = *(const float2*)&blin[d];

    float pm[3] = {};
    #pragma unroll
    for (int m = 0; m < C; m++) {
        #pragma unroll
        for (int j = 0; j < 6; j++) {
            float2 u = *(const float2*)&g_P[5 - j][1 + m][d];
            float2 a = *(const float2*)&g_a[j][b][d];
            pm[m] += u.x * a.x + u.y * a.y;
        }
        float2 u6 = *(const float2*)&g_P[6][1 + m][d];
        pm[m] += u6.x * v0.x + u6.y * v0.y;
        #pragma unroll
        for (int k = 0; k < 6; k++) {
            float2 uk = *(const float2*)&g_P[k][1 + m][d];
            pm[m] += uk.x * bl.x + uk.y * bl.y;
        }
    }
    block_multired<3>(pm, scr, res, t);
    if (t < C) out[b * C + t] = res[t] + bout[t];
}

// ---------------- launcher -------------------------------------------------------
extern "C" void kernel_launch(void* const* d_in, const int* in_sizes, int n_in,
                              void* d_out, int out_size) {
    const int*   ctx   = (const int*)d_in[0];
    const int*   tgt   = (const int*)d_in[1];
    const int*   clen  = (const int*)d_in[2];
    const int*   tlen  = (const int*)d_in[3];
    const int*   toff  = (const int*)d_in[4];
    const float* emb   = (const float*)d_in[5];
    const float* Wlin  = (const float*)d_in[6];
    const float* blin  = (const float*)d_in[7];
    const float* wattn = (const float*)d_in[8];
    const float* battn = (const float*)d_in[9];
    const float* Wout  = (const float*)d_in[10];
    const float* bout  = (const float*)d_in[11];
    float* out = (float*)d_out;

    proj_init_k<<<4, 256>>>(wattn, Wout);
    for (int k = 0; k < 6; k++)
        matvec4_k<<<1024, 256>>>(Wlin, k);

    vaspect_k<<<B, 256>>>(tgt, tlen, emb);
    precomputeA_k<<<dim3(B, L / 32), 256>>>(ctx, clen, toff, emb, wattn);
    scalar_k<<<B, 512>>>(clen, blin, battn);
    phaseC_k<<<NATTN, 256>>>(ctx, clen, emb);
    combineC_k<<<6 * B, 256>>>();
    logits_k<<<B, 512>>>(blin, bout, out);
}